// round 3
// baseline (speedup 1.0000x reference)
#include <cuda_runtime.h>
#include <cstdint>

#define NN 100000
#define EE 1280000
#define RR 8
#define DD 64
#define TT 50000

// ---- scratch (device globals: alloc-free rule) ----
__device__ float g_x[(size_t)NN * DD];        // 25.6 MB
__device__ float g_x2[(size_t)NN * DD];       // 25.6 MB
__device__ float g_h[(size_t)RR * NN * DD];   // 204.8 MB
__device__ float g_agg[(size_t)NN * DD];      // 25.6 MB
__device__ float g_deg[NN];
__device__ float g_invdeg[NN];

// ---- init: x = node_emb[x_idx] ----
__global__ void k_init_x(const int* __restrict__ x_idx, const float* __restrict__ emb) {
    int i = blockIdx.x * blockDim.x + threadIdx.x;   // over NN*16 float4s
    if (i >= NN * (DD / 4)) return;
    int n = i >> 4, c = i & 15;
    int s = x_idx[n];
    reinterpret_cast<float4*>(g_x)[(size_t)n * 16 + c] =
        reinterpret_cast<const float4*>(emb)[(size_t)s * 16 + c];
}

// ---- in-degree ----
__global__ void k_deg(const int* __restrict__ ei) {
    int e = blockIdx.x * blockDim.x + threadIdx.x;
    if (e < EE) atomicAdd(&g_deg[ei[EE + e]], 1.0f);
}

__global__ void k_invdeg() {
    int n = blockIdx.x * blockDim.x + threadIdx.x;
    if (n < NN) g_invdeg[n] = 1.0f / fmaxf(g_deg[n], 1.0f);
}

// ---- h[r] = x @ W[r] : 64-node tile per block, 4x4 register microtile ----
__global__ __launch_bounds__(256) void k_gemm_h(const float* __restrict__ W,
                                                const float* __restrict__ xin) {
    __shared__ float Ws[DD * DD];
    __shared__ float XsT[DD][DD + 1];
    int r = blockIdx.y;
    int n0 = blockIdx.x * 64;
    int tid = threadIdx.x;

    const float* Wr = W + (size_t)r * DD * DD;
    for (int i = tid; i < DD * DD / 4; i += 256)
        reinterpret_cast<float4*>(Ws)[i] = reinterpret_cast<const float4*>(Wr)[i];

    for (int i = tid; i < 64 * 16; i += 256) {
        int n = i >> 4, k4 = (i & 15) << 2;
        float4 v = make_float4(0.f, 0.f, 0.f, 0.f);
        if (n0 + n < NN)
            v = reinterpret_cast<const float4*>(xin + (size_t)(n0 + n) * DD)[k4 >> 2];
        XsT[k4 + 0][n] = v.x; XsT[k4 + 1][n] = v.y;
        XsT[k4 + 2][n] = v.z; XsT[k4 + 3][n] = v.w;
    }
    __syncthreads();

    int tx = tid & 15, ty = tid >> 4;
    float acc[4][4] = {};
#pragma unroll
    for (int k = 0; k < 64; k++) {
        float4 b = reinterpret_cast<const float4*>(Ws + k * DD)[tx];
        float bb[4] = {b.x, b.y, b.z, b.w};
        float a[4];
#pragma unroll
        for (int ii = 0; ii < 4; ii++) a[ii] = XsT[k][ty * 4 + ii];
#pragma unroll
        for (int ii = 0; ii < 4; ii++)
#pragma unroll
            for (int jj = 0; jj < 4; jj++)
                acc[ii][jj] += a[ii] * bb[jj];
    }

    float* outb = g_h + ((size_t)r * NN + n0) * DD;
#pragma unroll
    for (int ii = 0; ii < 4; ii++) {
        int n = ty * 4 + ii;
        if (n0 + n < NN)
            reinterpret_cast<float4*>(outb + (size_t)n * DD)[tx] =
                make_float4(acc[ii][0], acc[ii][1], acc[ii][2], acc[ii][3]);
    }
}

// ---- edge aggregation: warp per edge, vector RED into L2-resident agg ----
__global__ void k_edge(const int* __restrict__ ei, const int* __restrict__ et) {
    int warp = (blockIdx.x * blockDim.x + threadIdx.x) >> 5;
    int lane = threadIdx.x & 31;
    int nwarp = (gridDim.x * blockDim.x) >> 5;
    for (int e = warp; e < EE; e += nwarp) {
        int src = ei[e];
        int dst = ei[EE + e];
        int r   = et[e];
        const float2* row = reinterpret_cast<const float2*>(g_h + ((size_t)r * NN + src) * DD);
        float2 v = row[lane];
        float* dptr = g_agg + (size_t)dst * DD + lane * 2;
        asm volatile("red.global.add.v2.f32 [%0], {%1, %2};"
                     :: "l"(dptr), "f"(v.x), "f"(v.y) : "memory");
    }
}

// ---- update: x_out = relu(agg*inv_deg + x_in @ root + bias) ----
__global__ __launch_bounds__(256) void k_update(const float* __restrict__ root,
                                                const float* __restrict__ bias,
                                                const float* __restrict__ xin,
                                                float* __restrict__ xout) {
    __shared__ float Ws[DD * DD];
    __shared__ float XsT[DD][DD + 1];
    int n0 = blockIdx.x * 64;
    int tid = threadIdx.x;

    for (int i = tid; i < DD * DD / 4; i += 256)
        reinterpret_cast<float4*>(Ws)[i] = reinterpret_cast<const float4*>(root)[i];

    for (int i = tid; i < 64 * 16; i += 256) {
        int n = i >> 4, k4 = (i & 15) << 2;
        float4 v = make_float4(0.f, 0.f, 0.f, 0.f);
        if (n0 + n < NN)
            v = reinterpret_cast<const float4*>(xin + (size_t)(n0 + n) * DD)[k4 >> 2];
        XsT[k4 + 0][n] = v.x; XsT[k4 + 1][n] = v.y;
        XsT[k4 + 2][n] = v.z; XsT[k4 + 3][n] = v.w;
    }
    __syncthreads();

    int tx = tid & 15, ty = tid >> 4;
    float acc[4][4] = {};
#pragma unroll
    for (int k = 0; k < 64; k++) {
        float4 b = reinterpret_cast<const float4*>(Ws + k * DD)[tx];
        float bb[4] = {b.x, b.y, b.z, b.w};
        float a[4];
#pragma unroll
        for (int ii = 0; ii < 4; ii++) a[ii] = XsT[k][ty * 4 + ii];
#pragma unroll
        for (int ii = 0; ii < 4; ii++)
#pragma unroll
            for (int jj = 0; jj < 4; jj++)
                acc[ii][jj] += a[ii] * bb[jj];
    }

    float4 bs = reinterpret_cast<const float4*>(bias)[tx];
#pragma unroll
    for (int ii = 0; ii < 4; ii++) {
        int n = n0 + ty * 4 + ii;
        if (n < NN) {
            float id = g_invdeg[n];
            float4 ag = reinterpret_cast<const float4*>(g_agg + (size_t)n * DD)[tx];
            float4 o;
            o.x = fmaxf(acc[ii][0] + ag.x * id + bs.x, 0.f);
            o.y = fmaxf(acc[ii][1] + ag.y * id + bs.y, 0.f);
            o.z = fmaxf(acc[ii][2] + ag.z * id + bs.z, 0.f);
            o.w = fmaxf(acc[ii][3] + ag.w * id + bs.w, 0.f);
            reinterpret_cast<float4*>(xout + (size_t)n * DD)[tx] = o;
        }
    }
}

// ---- final: out[t] = dot(x[s_t], x[t_t]) ; warp per target ----
__global__ void k_score(const int* __restrict__ tei, float* __restrict__ out) {
    int warp = (blockIdx.x * blockDim.x + threadIdx.x) >> 5;
    int lane = threadIdx.x & 31;
    if (warp >= TT) return;
    int s = tei[warp];
    int t = tei[TT + warp];
    float2 a = reinterpret_cast<const float2*>(g_x + (size_t)s * DD)[lane];
    float2 b = reinterpret_cast<const float2*>(g_x + (size_t)t * DD)[lane];
    float p = a.x * b.x + a.y * b.y;
#pragma unroll
    for (int o = 16; o; o >>= 1) p += __shfl_xor_sync(0xffffffffu, p, o);
    if (lane == 0) out[warp] = p;
}

extern "C" void kernel_launch(void* const* d_in, const int* in_sizes, int n_in,
                              void* d_out, int out_size) {
    const int*   x_idx = (const int*)d_in[0];
    const int*   ei    = (const int*)d_in[1];   // [2, E]
    const int*   et    = (const int*)d_in[2];   // [E]
    const int*   tei   = (const int*)d_in[3];   // [2, T]
    const float* emb   = (const float*)d_in[4]; // [N, D]
    const float* W     = (const float*)d_in[5]; // [2, 8, 64, 64]
    const float* root  = (const float*)d_in[6]; // [2, 64, 64]
    const float* bias  = (const float*)d_in[7]; // [2, 64]
    float* out = (float*)d_out;

    void *p_deg, *p_agg, *p_x, *p_x2;
    cudaGetSymbolAddress(&p_deg, g_deg);
    cudaGetSymbolAddress(&p_agg, g_agg);
    cudaGetSymbolAddress(&p_x, g_x);
    cudaGetSymbolAddress(&p_x2, g_x2);
    float* px  = (float*)p_x;
    float* px2 = (float*)p_x2;

    cudaMemsetAsync(p_deg, 0, NN * sizeof(float), 0);
    k_init_x<<<(NN * 16 + 255) / 256, 256>>>(x_idx, emb);
    k_deg<<<(EE + 255) / 256, 256>>>(ei);
    k_invdeg<<<(NN + 255) / 256, 256>>>();

    int ntiles = (NN + 63) / 64;  // 1563
    for (int l = 0; l < 2; l++) {
        const float* xi = (l == 0) ? px : px2;
        float*       xo = (l == 0) ? px2 : px;
        k_gemm_h<<<dim3(ntiles, RR), 256>>>(W + (size_t)l * RR * DD * DD, xi);
        cudaMemsetAsync(p_agg, 0, (size_t)NN * DD * sizeof(float), 0);
        k_edge<<<4096, 256>>>(ei, et);
        k_update<<<ntiles, 256>>>(root + (size_t)l * DD * DD, bias + (size_t)l * DD, xi, xo);
    }
    k_score<<<(TT * 32 + 255) / 256, 256>>>(tei, out);
}

// round 5
// speedup vs baseline: 1.3269x; 1.3269x over previous
#include <cuda_runtime.h>
#include <cuda_bf16.h>
#include <cstdint>

#define NN 100000
#define EE 1280000
#define RR 8
#define DD 64
#define TT 50000

// ---- scratch (device globals: alloc-free rule) ----
__device__ float g_x[(size_t)NN * DD];        // 25.6 MB
__device__ float g_x2[(size_t)NN * DD];       // 25.6 MB
__device__ float g_h[(size_t)RR * NN * DD];   // 204.8 MB
__device__ float g_agg[(size_t)NN * DD];      // 25.6 MB
__device__ float g_deg[NN];
__device__ float g_invdeg[NN];
__device__ __nv_bfloat16 g_xh[(size_t)NN * DD];   // hi split of x
__device__ __nv_bfloat16 g_xl[(size_t)NN * DD];   // lo split of x
__device__ __nv_bfloat16 g_wh[2 * RR * DD * DD];  // W^T hi, [l][r][n][k]
__device__ __nv_bfloat16 g_wl[2 * RR * DD * DD];  // W^T lo

__device__ __forceinline__ uint32_t smem_u32(const void* p) {
    uint32_t a;
    asm("{ .reg .u64 t; cvta.to.shared.u64 t, %1; cvt.u32.u64 %0, t; }" : "=r"(a) : "l"(p));
    return a;
}

#define LDM_X4(r, addr)                                                          \
    asm volatile("ldmatrix.sync.aligned.m8n8.x4.shared.b16 {%0,%1,%2,%3}, [%4];" \
        : "=r"((r)[0]), "=r"((r)[1]), "=r"((r)[2]), "=r"((r)[3]) : "r"(addr))

#define LDM_X2(r, addr)                                                          \
    asm volatile("ldmatrix.sync.aligned.m8n8.x2.shared.b16 {%0,%1}, [%2];"       \
        : "=r"((r)[0]), "=r"((r)[1]) : "r"(addr))

#define MMA_BF16(c, a, b)                                                        \
    asm volatile("mma.sync.aligned.m16n8k16.row.col.f32.bf16.bf16.f32 "          \
        "{%0,%1,%2,%3}, {%4,%5,%6,%7}, {%8,%9}, {%0,%1,%2,%3};"                  \
        : "+f"((c)[0]), "+f"((c)[1]), "+f"((c)[2]), "+f"((c)[3])                 \
        : "r"((a)[0]), "r"((a)[1]), "r"((a)[2]), "r"((a)[3]),                    \
          "r"((b)[0]), "r"((b)[1]))

// ---- split helper ----
__device__ __forceinline__ void split_store(float v, __nv_bfloat16* hi, __nv_bfloat16* lo) {
    __nv_bfloat16 h = __float2bfloat16(v);
    *hi = h;
    *lo = __float2bfloat16(v - __bfloat162float(h));
}

// ---- init: x = node_emb[x_idx] (+ bf16 split) ----
__global__ void k_init_x(const int* __restrict__ x_idx, const float* __restrict__ emb) {
    int i = blockIdx.x * blockDim.x + threadIdx.x;
    if (i >= NN * (DD / 4)) return;
    int n = i >> 4, c = i & 15;
    int s = x_idx[n];
    float4 v = reinterpret_cast<const float4*>(emb)[(size_t)s * 16 + c];
    reinterpret_cast<float4*>(g_x)[(size_t)n * 16 + c] = v;
    size_t e = (size_t)n * DD + c * 4;
    split_store(v.x, &g_xh[e + 0], &g_xl[e + 0]);
    split_store(v.y, &g_xh[e + 1], &g_xl[e + 1]);
    split_store(v.z, &g_xh[e + 2], &g_xl[e + 2]);
    split_store(v.w, &g_xh[e + 3], &g_xl[e + 3]);
}

// ---- prep W: transpose + bf16 split, both layers ----
__global__ void k_prep_w(const float* __restrict__ W) {
    int idx = blockIdx.x * blockDim.x + threadIdx.x;
    if (idx >= 2 * RR * DD * DD) return;
    int k = idx & 63, n = (idx >> 6) & 63, r = (idx >> 12) & 7, l = idx >> 15;
    float v = W[(((size_t)l * RR + r) * DD + k) * DD + n];
    split_store(v, &g_wh[idx], &g_wl[idx]);
}

// ---- in-degree ----
__global__ void k_deg(const int* __restrict__ ei) {
    int e = blockIdx.x * blockDim.x + threadIdx.x;
    if (e < EE) atomicAdd(&g_deg[ei[EE + e]], 1.0f);
}
__global__ void k_invdeg() {
    int n = blockIdx.x * blockDim.x + threadIdx.x;
    if (n < NN) g_invdeg[n] = 1.0f / fmaxf(g_deg[n], 1.0f);
}

// ================= tensor-core h-GEMM via mma.sync (HMMA, base-target legal) ==
// Block: 256 threads (8 warps), tile = 128 nodes x 1 relation.
// h[r] = x @ W[r], split bf16: xh*Wh + xh*Wl + xl*Wh, fp32 accum.
// Smem rows padded to 72 bf16 (144B) -> ldmatrix conflict-free.
#define PAD 72
#define A_BYTES (128 * PAD * 2)   // 18432
#define W_BYTES (64 * PAD * 2)    // 9216
#define SM_AH 0
#define SM_AL A_BYTES
#define SM_WH (2 * A_BYTES)
#define SM_WL (2 * A_BYTES + W_BYTES)
#define SM_TOTAL (2 * A_BYTES + 2 * W_BYTES)  // 55296

__global__ __launch_bounds__(256)
void k_gemm_h_tc(const __nv_bfloat16* __restrict__ wh,
                 const __nv_bfloat16* __restrict__ wl) {
    extern __shared__ __align__(16) char sm[];
    int tid = threadIdx.x;
    int n0 = blockIdx.x * 128;
    int r  = blockIdx.y;

    // load A tiles (xh, xl): 128 rows x 64 bf16, padded stride
    const uint4 z4 = make_uint4(0, 0, 0, 0);
    for (int i = tid; i < 128 * 8; i += 256) {
        int row = i >> 3, c = i & 7;
        uint4 vh = z4, vl = z4;
        if (n0 + row < NN) {
            size_t g = (size_t)(n0 + row) * 8 + c;  // uint4 index (8 bf16 each)
            vh = reinterpret_cast<const uint4*>(g_xh)[g];
            vl = reinterpret_cast<const uint4*>(g_xl)[g];
        }
        *reinterpret_cast<uint4*>(sm + SM_AH + row * 144 + c * 16) = vh;
        *reinterpret_cast<uint4*>(sm + SM_AL + row * 144 + c * 16) = vl;
    }
    // load W^T tiles (hi, lo): 64 rows x 64 bf16
    for (int i = tid; i < 64 * 8; i += 256) {
        int row = i >> 3, c = i & 7;
        size_t g = (size_t)r * 512 + (size_t)row * 8 + c;  // uint4 idx into 64x64 tile
        *reinterpret_cast<uint4*>(sm + SM_WH + row * 144 + c * 16) =
            reinterpret_cast<const uint4*>(wh)[g];
        *reinterpret_cast<uint4*>(sm + SM_WL + row * 144 + c * 16) =
            reinterpret_cast<const uint4*>(wl)[g];
    }
    __syncthreads();

    uint32_t sb = smem_u32(sm);
    int w = tid >> 5, t = tid & 31;
    int tt = t & 15;

    float acc[8][4] = {};
    uint32_t a_row = w * 16 + (t & 15);
    uint32_t a_col_half = (t >> 4);           // 0/1 -> k offset 0/8 within 16
    uint32_t b_row = tt & 7;                  // n within 8-block
    uint32_t b_half = (tt >> 3) & 1;          // 0/1 -> k offset 0/8

#pragma unroll
    for (int kb = 0; kb < 4; kb++) {
        uint32_t aoff = a_row * 144 + (kb * 16 + a_col_half * 8) * 2;
        uint32_t ah[4], al[4];
        LDM_X4(ah, sb + SM_AH + aoff);
        LDM_X4(al, sb + SM_AL + aoff);
#pragma unroll
        for (int nb = 0; nb < 8; nb++) {
            uint32_t boff = (nb * 8 + b_row) * 144 + (kb * 16 + b_half * 8) * 2;
            uint32_t bh[2], bl[2];
            LDM_X2(bh, sb + SM_WH + boff);
            LDM_X2(bl, sb + SM_WL + boff);
            MMA_BF16(acc[nb], ah, bh);
            MMA_BF16(acc[nb], ah, bl);
            MMA_BF16(acc[nb], al, bh);
        }
    }

    // epilogue: thread t owns rows (t/4, t/4+8) of its warp's 16-row slab
    int row0 = n0 + w * 16 + (t >> 2);
    int col2 = (t & 3) * 2;
    float* hb = g_h + (size_t)r * NN * DD;
#pragma unroll
    for (int nb = 0; nb < 8; nb++) {
        int col = nb * 8 + col2;
        if (row0 < NN)
            *reinterpret_cast<float2*>(hb + (size_t)row0 * DD + col) =
                make_float2(acc[nb][0], acc[nb][1]);
        if (row0 + 8 < NN)
            *reinterpret_cast<float2*>(hb + (size_t)(row0 + 8) * DD + col) =
                make_float2(acc[nb][2], acc[nb][3]);
    }
}

// ---- edge aggregation: warp per edge, vector RED into L2-resident agg ----
__global__ void k_edge(const int* __restrict__ ei, const int* __restrict__ et) {
    int warp = (blockIdx.x * blockDim.x + threadIdx.x) >> 5;
    int lane = threadIdx.x & 31;
    int nwarp = (gridDim.x * blockDim.x) >> 5;
    for (int e = warp; e < EE; e += nwarp) {
        int src = ei[e];
        int dst = ei[EE + e];
        int r   = et[e];
        const float2* row = reinterpret_cast<const float2*>(g_h + ((size_t)r * NN + src) * DD);
        float2 v = row[lane];
        float* dptr = g_agg + (size_t)dst * DD + lane * 2;
        asm volatile("red.global.add.v2.f32 [%0], {%1, %2};"
                     :: "l"(dptr), "f"(v.x), "f"(v.y) : "memory");
    }
}

// ---- update: x_out = relu(agg*inv_deg + x_in @ root + bias), + bf16 split ----
__global__ __launch_bounds__(256) void k_update(const float* __restrict__ root,
                                                const float* __restrict__ bias,
                                                const float* __restrict__ xin,
                                                float* __restrict__ xout) {
    __shared__ float Ws[DD * DD];
    __shared__ float XsT[DD][DD + 1];
    int n0 = blockIdx.x * 64;
    int tid = threadIdx.x;

    for (int i = tid; i < DD * DD / 4; i += 256)
        reinterpret_cast<float4*>(Ws)[i] = reinterpret_cast<const float4*>(root)[i];

    for (int i = tid; i < 64 * 16; i += 256) {
        int n = i >> 4, k4 = (i & 15) << 2;
        float4 v = make_float4(0.f, 0.f, 0.f, 0.f);
        if (n0 + n < NN)
            v = reinterpret_cast<const float4*>(xin + (size_t)(n0 + n) * DD)[k4 >> 2];
        XsT[k4 + 0][n] = v.x; XsT[k4 + 1][n] = v.y;
        XsT[k4 + 2][n] = v.z; XsT[k4 + 3][n] = v.w;
    }
    __syncthreads();

    int tx = tid & 15, ty = tid >> 4;
    float acc[4][4] = {};
#pragma unroll
    for (int k = 0; k < 64; k++) {
        float4 b = reinterpret_cast<const float4*>(Ws + k * DD)[tx];
        float bb[4] = {b.x, b.y, b.z, b.w};
        float a[4];
#pragma unroll
        for (int ii = 0; ii < 4; ii++) a[ii] = XsT[k][ty * 4 + ii];
#pragma unroll
        for (int ii = 0; ii < 4; ii++)
#pragma unroll
            for (int jj = 0; jj < 4; jj++)
                acc[ii][jj] += a[ii] * bb[jj];
    }

    float4 bs = reinterpret_cast<const float4*>(bias)[tx];
#pragma unroll
    for (int ii = 0; ii < 4; ii++) {
        int n = n0 + ty * 4 + ii;
        if (n < NN) {
            float id = g_invdeg[n];
            float4 ag = reinterpret_cast<const float4*>(g_agg + (size_t)n * DD)[tx];
            float4 o;
            o.x = fmaxf(acc[ii][0] + ag.x * id + bs.x, 0.f);
            o.y = fmaxf(acc[ii][1] + ag.y * id + bs.y, 0.f);
            o.z = fmaxf(acc[ii][2] + ag.z * id + bs.z, 0.f);
            o.w = fmaxf(acc[ii][3] + ag.w * id + bs.w, 0.f);
            reinterpret_cast<float4*>(xout + (size_t)n * DD)[tx] = o;
            size_t e = (size_t)n * DD + tx * 4;
            split_store(o.x, &g_xh[e + 0], &g_xl[e + 0]);
            split_store(o.y, &g_xh[e + 1], &g_xl[e + 1]);
            split_store(o.z, &g_xh[e + 2], &g_xl[e + 2]);
            split_store(o.w, &g_xh[e + 3], &g_xl[e + 3]);
        }
    }
}

// ---- final: out[t] = dot(x[s_t], x[t_t]) ; warp per target ----
__global__ void k_score(const int* __restrict__ tei, const float* __restrict__ x,
                        float* __restrict__ out) {
    int warp = (blockIdx.x * blockDim.x + threadIdx.x) >> 5;
    int lane = threadIdx.x & 31;
    if (warp >= TT) return;
    int s = tei[warp];
    int t = tei[TT + warp];
    float2 a = reinterpret_cast<const float2*>(x + (size_t)s * DD)[lane];
    float2 b = reinterpret_cast<const float2*>(x + (size_t)t * DD)[lane];
    float p = a.x * b.x + a.y * b.y;
#pragma unroll
    for (int o = 16; o; o >>= 1) p += __shfl_xor_sync(0xffffffffu, p, o);
    if (lane == 0) out[warp] = p;
}

extern "C" void kernel_launch(void* const* d_in, const int* in_sizes, int n_in,
                              void* d_out, int out_size) {
    const int*   x_idx = (const int*)d_in[0];
    const int*   ei    = (const int*)d_in[1];
    const int*   et    = (const int*)d_in[2];
    const int*   tei   = (const int*)d_in[3];
    const float* emb   = (const float*)d_in[4];
    const float* W     = (const float*)d_in[5];
    const float* root  = (const float*)d_in[6];
    const float* bias  = (const float*)d_in[7];
    float* out = (float*)d_out;

    cudaFuncSetAttribute(k_gemm_h_tc, cudaFuncAttributeMaxDynamicSharedMemorySize, SM_TOTAL);

    void *p_deg, *p_agg, *p_x, *p_x2, *p_wh, *p_wl;
    cudaGetSymbolAddress(&p_deg, g_deg);
    cudaGetSymbolAddress(&p_agg, g_agg);
    cudaGetSymbolAddress(&p_x, g_x);
    cudaGetSymbolAddress(&p_x2, g_x2);
    cudaGetSymbolAddress(&p_wh, g_wh);
    cudaGetSymbolAddress(&p_wl, g_wl);
    float* px  = (float*)p_x;
    float* px2 = (float*)p_x2;
    const __nv_bfloat16* wh = (const __nv_bfloat16*)p_wh;
    const __nv_bfloat16* wl = (const __nv_bfloat16*)p_wl;

    cudaMemsetAsync(p_deg, 0, NN * sizeof(float), 0);
    k_init_x<<<(NN * 16 + 255) / 256, 256>>>(x_idx, emb);
    k_prep_w<<<(2 * RR * DD * DD + 255) / 256, 256>>>(W);
    k_deg<<<(EE + 255) / 256, 256>>>(ei);
    k_invdeg<<<(NN + 255) / 256, 256>>>();

    int htiles = (NN + 127) / 128;  // 782
    int utiles = (NN + 63) / 64;    // 1563
    for (int l = 0; l < 2; l++) {
        const float* xi = (l == 0) ? px : px2;
        float*       xo = (l == 0) ? px2 : px;
        k_gemm_h_tc<<<dim3(htiles, RR), 256, SM_TOTAL>>>(
            wh + (size_t)l * RR * DD * DD, wl + (size_t)l * RR * DD * DD);
        cudaMemsetAsync(p_agg, 0, (size_t)NN * DD * sizeof(float), 0);
        k_edge<<<4096, 256>>>(ei, et);
        k_update<<<utiles, 256>>>(root + (size_t)l * DD * DD, bias + (size_t)l * DD, xi, xo);
    }
    k_score<<<(TT * 32 + 255) / 256, 256>>>(tei, px, out);
}